// round 9
// baseline (speedup 1.0000x reference)
#include <cuda_runtime.h>

#define DIM 4096
#define NQ 12
#define DEPTH 4

// sigma (gather form of the CNOT ring, verified R1-R8):
// bit_i = x_i^x_{i+1} (i<=9), bit10 = x10^x11^x0, bit11 = x11^x0.
__host__ __device__ __forceinline__ constexpr int sig(int x) {
    int r = (x ^ (x >> 1)) & 0x3FF;
    r |= (((x >> 10) ^ (x >> 11) ^ x) & 1) << 10;
    r |= (((x >> 11) ^ x) & 1) << 11;
    return r;
}
// sigma^{-1} (for store-side fusion): y_i = parity(x_i..x_11) for i=1..10,
// y_0 = parity(all), y_11 = parity(x_0..x_10).  Verified sig(sig_inv(x))==x
// on basis vectors by hand (x=0x800 -> 0x7FF -> 0x800; x=1 -> 0x801 -> 1).
__host__ __device__ __forceinline__ constexpr int sig_inv(int x) {
    int y = 0, suf = 0;
    for (int i = 11; i >= 1; --i) {
        suf ^= (x >> i) & 1;
        if (i <= 10) y |= suf << i;
    }
    const int all = suf ^ (x & 1);
    y |= all;                          // bit 0
    y |= (all ^ ((x >> 11) & 1)) << 11;
    return y;
}
// Single placement for both buffers: fold bits 4-6 into bits 2-4.
// Preserves bits 0-1 (16B blocks intact -> LDS.128/STS.128 legal).
// Conflict-freedom (hand-verified full-rank lane->bank maps):
//  * A-load/readout/A-store (j = wid<<9|lane<<4|k): per-phase chunk-bank
//    (kq0^lane0, kq1^lane1, lane0^lane2) rank-3.
//  * B-load (i = wid<<5|lane, +k<<8): banks (i0,i1,i2^i4,i3,i4) rank-5.
//  * B-store/init (PH(sig_inv(i))): banks {11111,01111,00110,00011,00001} rank-5.
__host__ __device__ __forceinline__ constexpr int PH(int j) {
    return j ^ (((j >> 4) & 7) << 2);
}

__global__ __launch_bounds__(256, 1)
void qsim_kernel(const float* __restrict__ x, const float* __restrict__ theta,
                 const float* __restrict__ w, const float* __restrict__ b,
                 float* __restrict__ out) {
    __shared__ __align__(16) float S0[DIM];   // inter-layer buffer
    __shared__ __align__(16) float S1[DIM];   // intra-layer buffer
    __shared__ float CS[DEPTH * NQ];  // cos(a)
    __shared__ float SN[DEPTH * NQ];  // sin(a)
    __shared__ float TN[DEPTH * NQ];  // tan(a/2) = s/(1+c)  (lifting shear)
    __shared__ float red[16];

    const int tid = threadIdx.x;
    const int lane = tid & 31;
    const int wid = tid >> 5;   // 0..7

    // half-angle tables: a[d][q] = (theta[d][q] + 0.1*x[q]) / 2
    if (tid < DEPTH * NQ) {
        const int q = tid % NQ;
        float s, c;
        __sincosf(0.5f * (theta[tid] + 0.1f * x[q]), &s, &c);
        CS[tid] = c;
        SN[tid] = s;
        TN[tid] = s / (1.f + c);
    }
    __syncthreads();

    // Layout A: j = wid<<9 | lane<<4 | k   (k bits 0-3, lane bits 4-8, wid 9-11)
    // Layout B: i = wid<<5 | lane | k<<8   (lane bits 0-4, wid bits 5-7, k bits 8-11)
    const int baseA = (wid << 9) | (lane << 4);
    const int baseB = (wid << 5) | lane;

    // d-invariant addresses
    int aAddr[4];                      // A-load/A-store/readout 128-bit chunks
#pragma unroll
    for (int kq = 0; kq < 4; ++kq) aAddr[kq] = PH(baseA | (kq << 2));
    const int bAddr = PH(baseB);       // B-load base; offsets +256k (PH k-invariant here)
    int sbAddr[16];                    // B-store/init: PH(sig_inv(i)), linear in i
    {
        const int s0 = PH(sig_inv(baseB));
#pragma unroll
        for (int k = 0; k < 16; ++k) sbAddr[k] = s0 ^ PH(sig_inv(k << 8));
    }

    float v[16];

    // ============ Layer 0: product state (12 RYs on e0), ring-0 fused in store ====
    {
        float P = 1.f;
#pragma unroll
        for (int bp = 0; bp < 8; ++bp)            // i bit bp -> qubit 11-bp
            P *= ((baseB >> bp) & 1) ? SN[11 - bp] : CS[11 - bp];
        float t01[4], t23[4];
#pragma unroll
        for (int t = 0; t < 4; ++t) {
            t01[t] = ((t & 1) ? SN[3] : CS[3]) * ((t & 2) ? SN[2] : CS[2]);
            t23[t] = ((t & 1) ? SN[1] : CS[1]) * ((t & 2) ? SN[0] : CS[0]);
        }
#pragma unroll
        for (int k = 0; k < 16; ++k)
            S0[sbAddr[k]] = P * t01[k & 3] * t23[k >> 2];
    }
    __syncthreads();

    // ============ Layers 1..3 ============
#pragma unroll
    for (int d = 1; d < DEPTH; ++d) {
        const float* C = CS + d * NQ;
        const float* Sn = SN + d * NQ;
        const float* Tn = TN + d * NQ;

        // ---- Pass A: vector gather (plain; prev ring was store-fused),
        //      rotate qubits 11,10,9,8 (k bits, lifting) + 7,6,5,4 (lane shfl),
        //      vector scatter to S1.
#pragma unroll
        for (int kq = 0; kq < 4; ++kq) {
            const float4 p = *reinterpret_cast<const float4*>(&S0[aAddr[kq]]);
            v[4 * kq] = p.x; v[4 * kq + 1] = p.y; v[4 * kq + 2] = p.z; v[4 * kq + 3] = p.w;
        }
#pragma unroll
        for (int rb = 0; rb < 4; ++rb) {          // k bit rb -> qubit 11-rb
            const int m = 1 << rb;
            const float s = Sn[11 - rb], t = Tn[11 - rb];
#pragma unroll
            for (int k = 0; k < 16; ++k)
                if (!(k & m)) {
                    const float lo = v[k], hi = v[k | m];
                    const float x1 = fmaf(-t, hi, lo);
                    const float y1 = fmaf(s, x1, hi);
                    v[k]     = fmaf(-t, y1, x1);  // = c*lo - s*hi
                    v[k | m] = y1;                // = s*lo + c*hi
                }
        }
#pragma unroll
        for (int bs = 0; bs < 4; ++bs) {          // lane bit bs -> j bit 4+bs -> qubit 7-bs
            const int m = 1 << bs;
            const float c = C[7 - bs], s = Sn[7 - bs];
            const float se = (lane & m) ? s : -s;
#pragma unroll
            for (int k = 0; k < 16; ++k) {
                const float o = __shfl_xor_sync(0xffffffffu, v[k], m);
                v[k] = c * v[k] + se * o;
            }
        }
#pragma unroll
        for (int kq = 0; kq < 4; ++kq)
            *reinterpret_cast<float4*>(&S1[aAddr[kq]]) =
                make_float4(v[4 * kq], v[4 * kq + 1], v[4 * kq + 2], v[4 * kq + 3]);
        __syncthreads();

        // ---- Pass B: scalar gather (immediate offsets), rotate qubits 3,2,1,0
        //      (k bits, lifting), scatter with ring-d fused (sig_inv addresses).
#pragma unroll
        for (int k = 0; k < 16; ++k) v[k] = S1[bAddr + (k << 8)];

#pragma unroll
        for (int rb = 0; rb < 4; ++rb) {          // k bit rb -> i bit 8+rb -> qubit 3-rb
            const int m = 1 << rb;
            const float s = Sn[3 - rb], t = Tn[3 - rb];
#pragma unroll
            for (int k = 0; k < 16; ++k)
                if (!(k & m)) {
                    const float lo = v[k], hi = v[k | m];
                    const float x1 = fmaf(-t, hi, lo);
                    const float y1 = fmaf(s, x1, hi);
                    v[k]     = fmaf(-t, y1, x1);
                    v[k | m] = y1;
                }
        }
#pragma unroll
        for (int k = 0; k < 16; ++k) S0[sbAddr[k]] = v[k];
        __syncthreads();
    }

    // ============ Readout: plain vector gather (final ring already fused) ========
    float a0 = 0.f, a1 = 0.f;
#pragma unroll
    for (int kq = 0; kq < 4; ++kq) {
        const float4 p = *reinterpret_cast<const float4*>(&S0[aAddr[kq]]);
        v[4 * kq] = p.x; v[4 * kq + 1] = p.y; v[4 * kq + 2] = p.z; v[4 * kq + 3] = p.w;
    }
#pragma unroll
    for (int m2 = 0; m2 < 8; ++m2)   // state out: 8B-aligned pairs
        *reinterpret_cast<float2*>(out + 2 + baseA + 2 * m2) =
            make_float2(v[2 * m2], v[2 * m2 + 1]);
#pragma unroll
    for (int kq = 0; kq < 4; ++kq) {
        const float4 w0 = *reinterpret_cast<const float4*>(w + baseA + 4 * kq);
        const float4 w1 = *reinterpret_cast<const float4*>(w + DIM + baseA + 4 * kq);
        const float p0 = v[4 * kq] * v[4 * kq];
        const float p1 = v[4 * kq + 1] * v[4 * kq + 1];
        const float p2 = v[4 * kq + 2] * v[4 * kq + 2];
        const float p3 = v[4 * kq + 3] * v[4 * kq + 3];
        a0 += p0 * w0.x + p1 * w0.y + p2 * w0.z + p3 * w0.w;
        a1 += p0 * w1.x + p1 * w1.y + p2 * w1.z + p3 * w1.w;
    }
#pragma unroll
    for (int o = 16; o > 0; o >>= 1) {
        a0 += __shfl_down_sync(0xffffffffu, a0, o);
        a1 += __shfl_down_sync(0xffffffffu, a1, o);
    }
    if (lane == 0) { red[wid] = a0; red[8 + wid] = a1; }
    __syncthreads();
    if (wid == 0 && lane < 16) {
        float rr = (lane < 8) ? red[lane] : red[8 + (lane & 7)];
#pragma unroll
        for (int o = 4; o > 0; o >>= 1)
            rr += __shfl_down_sync(0x0000ffffu, rr, o);
        if (lane == 0) out[0] = rr + b[0];
        if (lane == 8) out[1] = rr + b[1];
    }
}

extern "C" void kernel_launch(void* const* d_in, const int* in_sizes, int n_in,
                              void* d_out, int out_size) {
    const float* x = nullptr;
    const float* th = nullptr;
    const float* w = nullptr;
    const float* b = nullptr;
    for (int i = 0; i < n_in; ++i) {
        const int s = in_sizes[i];
        if (s == NQ) x = (const float*)d_in[i];
        else if (s == DEPTH * NQ) th = (const float*)d_in[i];
        else if (s == 2 * DIM) w = (const float*)d_in[i];
        else if (s == 2) b = (const float*)d_in[i];
    }
    qsim_kernel<<<1, 256>>>(x, th, w, b, (float*)d_out);
}

// round 10
// speedup vs baseline: 1.0307x; 1.0307x over previous
#include <cuda_runtime.h>

#define DIM 4096
#define NQ 12
#define DEPTH 4

// sigma^{-1} of the CNOT ring (store-side fusion), GF(2)-linear, verified in R9
// (kernel passed with identical mapping): y_i = parity(x_i..x11) for i=1..10,
// y_0 = parity(all), y_11 = parity(x_0..x_10).
__host__ __device__ __forceinline__ constexpr int sig_inv(int x) {
    int y = 0, suf = 0;
    for (int i = 11; i >= 1; --i) {
        suf ^= (x >> i) & 1;
        if (i <= 10) y |= suf << i;
    }
    const int all = suf ^ (x & 1);
    y |= all;
    y |= (all ^ ((x >> 11) & 1)) << 11;
    return y;
}
// Placement (both buffers): fold bits 4-6 into bits 2-4; preserves bits 0-1
// (16B blocks intact -> LDS.128/STS.128). All access patterns verified
// conflict-free in R9 (passed) + re-derived by hand this round.
__host__ __device__ __forceinline__ constexpr int PH(int j) {
    return j ^ (((j >> 4) & 7) << 2);
}
// PH(sig_inv(k<<8)) basis images (hand-computed, checked sig(0x7FF)=0x800):
//   k bit0 (i bit8):  PH(0x9FF)=0x9E3   k bit1: PH(0xBFF)=0xBE3
//   k bit2:           PH(0xFFF)=0xFE3   k bit3: PH(0x7FF)=0x7E3
__host__ __device__ __forceinline__ constexpr int KC(int k) {
    return ((k & 1) ? 0x9E3 : 0) ^ ((k & 2) ? 0xBE3 : 0)
         ^ ((k & 4) ? 0xFE3 : 0) ^ ((k & 8) ? 0x7E3 : 0);
}

__global__ __launch_bounds__(256, 1)
void qsim_kernel(const float* __restrict__ x, const float* __restrict__ theta,
                 const float* __restrict__ w, const float* __restrict__ b,
                 float* __restrict__ out) {
    __shared__ __align__(16) float S0[DIM];   // inter-layer buffer
    __shared__ __align__(16) float S1[DIM];   // intra-layer buffer
    __shared__ float CS[DEPTH * NQ];
    __shared__ float SN[DEPTH * NQ];
    __shared__ float red[16];

    const int tid = threadIdx.x;
    const int lane = tid & 31;
    const int wid = tid >> 5;   // 0..7

    // half-angle tables
    if (tid < DEPTH * NQ) {
        const int q = tid % NQ;
        float s, c;
        __sincosf(0.5f * (theta[tid] + 0.1f * x[q]), &s, &c);
        CS[tid] = c;
        SN[tid] = s;
    }
    __syncthreads();

    // Layout A: j = wid<<9 | lane<<4 | k   (k bits 0-3 = qubits 11..8,
    //           lane bits 4-8 = qubits 7..3, wid bits 9-11)
    // Layout B: i = wid<<5 | lane | k<<8   (lane bits 0-4, wid 5-7, k 8-11 = qubits 3..0)
    const int baseA = (wid << 9) | (lane << 4);
    const int baseB = (wid << 5) | lane;

    int aAddr[4];                       // A-side 128-bit chunk addresses (d-invariant)
#pragma unroll
    for (int kq = 0; kq < 4; ++kq) aAddr[kq] = PH(baseA | (kq << 2));
    const int bAddr = PH(baseB);        // B-load base; +256k (PH k-invariant here)
    const int s0 = PH(sig_inv(baseB));  // B-store base; ^KC(k) compile-time consts

    float v[16];

    // ============ Layer 0: product state (12 RYs on e0), ring-0 fused in store ====
    {
        float P = 1.f;
#pragma unroll
        for (int bp = 0; bp < 8; ++bp)             // i bit bp -> qubit 11-bp
            P *= ((baseB >> bp) & 1) ? SN[11 - bp] : CS[11 - bp];
        float t01[4], t23[4];
#pragma unroll
        for (int t = 0; t < 4; ++t) {
            t01[t] = ((t & 1) ? SN[3] : CS[3]) * ((t & 2) ? SN[2] : CS[2]);
            t23[t] = ((t & 1) ? SN[1] : CS[1]) * ((t & 2) ? SN[0] : CS[0]);
        }
#pragma unroll
        for (int k = 0; k < 16; ++k)
            S0[s0 ^ KC(k)] = P * t01[k & 3] * t23[k >> 2];
    }
    __syncthreads();

    // ============ Layers 1..3 ============
#pragma unroll
    for (int d = 1; d < DEPTH; ++d) {
        const float* C = CS + d * NQ;
        const float* Sn = SN + d * NQ;

        // ---- Pass A: float4 gather (plain; prev ring was store-fused),
        //      rotate qubits 11..8 (k bits, in-reg) + 7..4 (lane shfl),
        //      float4 scatter to S1.
#pragma unroll
        for (int kq = 0; kq < 4; ++kq) {
            const float4 p = *reinterpret_cast<const float4*>(&S0[aAddr[kq]]);
            v[4 * kq] = p.x; v[4 * kq + 1] = p.y; v[4 * kq + 2] = p.z; v[4 * kq + 3] = p.w;
        }
#pragma unroll
        for (int rb = 0; rb < 4; ++rb) {           // k bit rb -> qubit 11-rb
            const int m = 1 << rb;
            const float c = C[11 - rb], s = Sn[11 - rb];
#pragma unroll
            for (int k = 0; k < 16; ++k)
                if (!(k & m)) {
                    const float lo = v[k], hi = v[k | m];
                    v[k]     = fmaf(c, lo, -s * hi);   // depth-2, parallel
                    v[k | m] = fmaf(s, lo,  c * hi);
                }
        }
#pragma unroll
        for (int bs = 0; bs < 4; ++bs) {           // lane bit bs -> qubit 7-bs
            const int m = 1 << bs;
            const float c = C[7 - bs], s = Sn[7 - bs];
            const float se = (lane & m) ? s : -s;
#pragma unroll
            for (int k = 0; k < 16; ++k) {
                const float o = __shfl_xor_sync(0xffffffffu, v[k], m);
                v[k] = fmaf(c, v[k], se * o);
            }
        }
#pragma unroll
        for (int kq = 0; kq < 4; ++kq)
            *reinterpret_cast<float4*>(&S1[aAddr[kq]]) =
                make_float4(v[4 * kq], v[4 * kq + 1], v[4 * kq + 2], v[4 * kq + 3]);
        __syncthreads();

        // ---- Pass B: scalar gather (immediate +256k), rotate qubits 3..0
        //      (k bits, in-reg), scatter with ring-d fused (constant XORs).
#pragma unroll
        for (int k = 0; k < 16; ++k) v[k] = S1[bAddr + (k << 8)];

#pragma unroll
        for (int rb = 0; rb < 4; ++rb) {           // k bit rb -> qubit 3-rb
            const int m = 1 << rb;
            const float c = C[3 - rb], s = Sn[3 - rb];
#pragma unroll
            for (int k = 0; k < 16; ++k)
                if (!(k & m)) {
                    const float lo = v[k], hi = v[k | m];
                    v[k]     = fmaf(c, lo, -s * hi);
                    v[k | m] = fmaf(s, lo,  c * hi);
                }
        }
#pragma unroll
        for (int k = 0; k < 16; ++k) S0[s0 ^ KC(k)] = v[k];
        __syncthreads();
    }

    // ============ Readout: float4 gather (final ring already fused) ========
    float a0 = 0.f, a1 = 0.f;
#pragma unroll
    for (int kq = 0; kq < 4; ++kq) {
        const float4 p = *reinterpret_cast<const float4*>(&S0[aAddr[kq]]);
        v[4 * kq] = p.x; v[4 * kq + 1] = p.y; v[4 * kq + 2] = p.z; v[4 * kq + 3] = p.w;
    }
#pragma unroll
    for (int m2 = 0; m2 < 8; ++m2)   // state out: 8B-aligned pairs
        *reinterpret_cast<float2*>(out + 2 + baseA + 2 * m2) =
            make_float2(v[2 * m2], v[2 * m2 + 1]);
#pragma unroll
    for (int kq = 0; kq < 4; ++kq) {
        const float4 w0 = *reinterpret_cast<const float4*>(w + baseA + 4 * kq);
        const float4 w1 = *reinterpret_cast<const float4*>(w + DIM + baseA + 4 * kq);
        const float p0 = v[4 * kq] * v[4 * kq];
        const float p1 = v[4 * kq + 1] * v[4 * kq + 1];
        const float p2 = v[4 * kq + 2] * v[4 * kq + 2];
        const float p3 = v[4 * kq + 3] * v[4 * kq + 3];
        a0 += p0 * w0.x + p1 * w0.y + p2 * w0.z + p3 * w0.w;
        a1 += p0 * w1.x + p1 * w1.y + p2 * w1.z + p3 * w1.w;
    }
#pragma unroll
    for (int o = 16; o > 0; o >>= 1) {
        a0 += __shfl_down_sync(0xffffffffu, a0, o);
        a1 += __shfl_down_sync(0xffffffffu, a1, o);
    }
    if (lane == 0) { red[wid] = a0; red[8 + wid] = a1; }
    __syncthreads();
    if (wid == 0 && lane < 16) {
        float rr = (lane < 8) ? red[lane] : red[8 + (lane & 7)];
#pragma unroll
        for (int o = 4; o > 0; o >>= 1)
            rr += __shfl_down_sync(0x0000ffffu, rr, o);
        if (lane == 0) out[0] = rr + b[0];
        if (lane == 8) out[1] = rr + b[1];
    }
}

extern "C" void kernel_launch(void* const* d_in, const int* in_sizes, int n_in,
                              void* d_out, int out_size) {
    const float* x = nullptr;
    const float* th = nullptr;
    const float* w = nullptr;
    const float* b = nullptr;
    for (int i = 0; i < n_in; ++i) {
        const int s = in_sizes[i];
        if (s == NQ) x = (const float*)d_in[i];
        else if (s == DEPTH * NQ) th = (const float*)d_in[i];
        else if (s == 2 * DIM) w = (const float*)d_in[i];
        else if (s == 2) b = (const float*)d_in[i];
    }
    qsim_kernel<<<1, 256>>>(x, th, w, b, (float*)d_out);
}

// round 11
// speedup vs baseline: 1.2353x; 1.1985x over previous
#include <cuda_runtime.h>

#define DIM 4096
#define NQ 12
#define DEPTH 4

// sigma^{-1} of the CNOT ring (store-side fusion), GF(2)-linear, verified R9/R10.
__host__ __device__ __forceinline__ constexpr int sig_inv(int x) {
    int y = 0, suf = 0;
    for (int i = 11; i >= 1; --i) {
        suf ^= (x >> i) & 1;
        if (i <= 10) y |= suf << i;
    }
    const int all = suf ^ (x & 1);
    y |= all;
    y |= (all ^ ((x >> 11) & 1)) << 11;
    return y;
}
// Placement (both buffers): fold bits 4-6 into bits 2-4; preserves bits 0-1
// (LDS.128/STS.128 legal). All access patterns conflict-free (verified R9/R10).
__host__ __device__ __forceinline__ constexpr int PH(int j) {
    return j ^ (((j >> 4) & 7) << 2);
}
// PH(sig_inv(k<<8)) basis images (verified R10, kernel passed):
__host__ __device__ __forceinline__ constexpr int KC(int k) {
    return ((k & 1) ? 0x9E3 : 0) ^ ((k & 2) ? 0xBE3 : 0)
         ^ ((k & 4) ? 0xFE3 : 0) ^ ((k & 8) ? 0x7E3 : 0);
}

__global__ __launch_bounds__(256, 1)
void qsim_kernel(const float* __restrict__ x, const float* __restrict__ theta,
                 const float* __restrict__ w, const float* __restrict__ b,
                 float* __restrict__ out) {
    __shared__ __align__(16) float S0[DIM];   // inter-layer buffer
    __shared__ __align__(16) float S1[DIM];   // intra-layer buffer
    __shared__ float CS[DEPTH * NQ];
    __shared__ float SN[DEPTH * NQ];
    __shared__ float red[16];

    const int tid = threadIdx.x;
    const int lane = tid & 31;
    const int wid = tid >> 5;   // 0..7

    // half-angle tables
    if (tid < DEPTH * NQ) {
        const int q = tid % NQ;
        float s, c;
        __sincosf(0.5f * (theta[tid] + 0.1f * x[q]), &s, &c);
        CS[tid] = c;
        SN[tid] = s;
    }
    __syncthreads();

    // Layout A: j = wid<<9 | lane<<4 | k   (k bits 0-3 = qubits 11..8,
    //           lane bits 4-8 = qubits 7..4 (+bit8), wid bits 9-11)
    // Layout B: i = wid<<5 | lane | k<<8   (lane bits 0-4, wid 5-7, k 8-11 = qubits 3..0)
    const int baseA = (wid << 9) | (lane << 4);
    const int baseB = (wid << 5) | lane;

    int aAddr[4];                       // A-side 128-bit chunk addresses (d-invariant)
#pragma unroll
    for (int kq = 0; kq < 4; ++kq) aAddr[kq] = PH(baseA | (kq << 2));
    const int bAddr = PH(baseB);        // B-load base; +256k (PH k-invariant here)
    const int s0 = PH(sig_inv(baseB));  // B-store base; ^KC(k) compile-time consts

    float v[16];

    // ============ Layer 0: product state (12 RYs on e0), ring-0 fused in store ====
    {
        float P = 1.f;
#pragma unroll
        for (int bp = 0; bp < 8; ++bp)             // i bit bp -> qubit 11-bp
            P *= ((baseB >> bp) & 1) ? SN[11 - bp] : CS[11 - bp];
        float t01[4], t23[4];
#pragma unroll
        for (int t = 0; t < 4; ++t) {
            t01[t] = ((t & 1) ? SN[3] : CS[3]) * ((t & 2) ? SN[2] : CS[2]);
            t23[t] = ((t & 1) ? SN[1] : CS[1]) * ((t & 2) ? SN[0] : CS[0]);
        }
#pragma unroll
        for (int k = 0; k < 16; ++k)
            S0[s0 ^ KC(k)] = P * t01[k & 3] * t23[k >> 2];
    }
    __syncthreads();

    // ============ Layers 1..3 — ROLLED: keep body ~1 layer to fit I$ and
    //              avoid the single-CTA >32KB issue throttle ============
#pragma unroll 1
    for (int d = 1; d < DEPTH; ++d) {
        const float* C = CS + d * NQ;
        const float* Sn = SN + d * NQ;

        // ---- Pass A: float4 gather (plain; prev ring was store-fused),
        //      rotate qubits 11..8 (k bits, in-reg) + 7..4 (lane shfl),
        //      float4 scatter to S1.
#pragma unroll
        for (int kq = 0; kq < 4; ++kq) {
            const float4 p = *reinterpret_cast<const float4*>(&S0[aAddr[kq]]);
            v[4 * kq] = p.x; v[4 * kq + 1] = p.y; v[4 * kq + 2] = p.z; v[4 * kq + 3] = p.w;
        }
#pragma unroll
        for (int rb = 0; rb < 4; ++rb) {           // k bit rb -> qubit 11-rb
            const int m = 1 << rb;
            const float c = C[11 - rb], s = Sn[11 - rb];
#pragma unroll
            for (int k = 0; k < 16; ++k)
                if (!(k & m)) {
                    const float lo = v[k], hi = v[k | m];
                    v[k]     = fmaf(c, lo, -s * hi);
                    v[k | m] = fmaf(s, lo,  c * hi);
                }
        }
#pragma unroll
        for (int bs = 0; bs < 4; ++bs) {           // lane bit bs -> qubit 7-bs
            const int m = 1 << bs;
            const float c = C[7 - bs], s = Sn[7 - bs];
            const float se = (lane & m) ? s : -s;
#pragma unroll
            for (int k = 0; k < 16; ++k) {
                const float o = __shfl_xor_sync(0xffffffffu, v[k], m);
                v[k] = fmaf(c, v[k], se * o);
            }
        }
#pragma unroll
        for (int kq = 0; kq < 4; ++kq)
            *reinterpret_cast<float4*>(&S1[aAddr[kq]]) =
                make_float4(v[4 * kq], v[4 * kq + 1], v[4 * kq + 2], v[4 * kq + 3]);
        __syncthreads();

        // ---- Pass B: scalar gather (immediate +256k), rotate qubits 3..0
        //      (k bits, in-reg), scatter with ring-d fused (constant XORs).
#pragma unroll
        for (int k = 0; k < 16; ++k) v[k] = S1[bAddr + (k << 8)];

#pragma unroll
        for (int rb = 0; rb < 4; ++rb) {           // k bit rb -> qubit 3-rb
            const int m = 1 << rb;
            const float c = C[3 - rb], s = Sn[3 - rb];
#pragma unroll
            for (int k = 0; k < 16; ++k)
                if (!(k & m)) {
                    const float lo = v[k], hi = v[k | m];
                    v[k]     = fmaf(c, lo, -s * hi);
                    v[k | m] = fmaf(s, lo,  c * hi);
                }
        }
#pragma unroll
        for (int k = 0; k < 16; ++k) S0[s0 ^ KC(k)] = v[k];
        __syncthreads();
    }

    // ============ Readout: float4 gather (final ring already fused) ========
    float a0 = 0.f, a1 = 0.f;
#pragma unroll
    for (int kq = 0; kq < 4; ++kq) {
        const float4 p = *reinterpret_cast<const float4*>(&S0[aAddr[kq]]);
        v[4 * kq] = p.x; v[4 * kq + 1] = p.y; v[4 * kq + 2] = p.z; v[4 * kq + 3] = p.w;
    }
#pragma unroll
    for (int m2 = 0; m2 < 8; ++m2)   // state out: 8B-aligned pairs
        *reinterpret_cast<float2*>(out + 2 + baseA + 2 * m2) =
            make_float2(v[2 * m2], v[2 * m2 + 1]);
#pragma unroll
    for (int kq = 0; kq < 4; ++kq) {
        const float4 w0 = *reinterpret_cast<const float4*>(w + baseA + 4 * kq);
        const float4 w1 = *reinterpret_cast<const float4*>(w + DIM + baseA + 4 * kq);
        const float p0 = v[4 * kq] * v[4 * kq];
        const float p1 = v[4 * kq + 1] * v[4 * kq + 1];
        const float p2 = v[4 * kq + 2] * v[4 * kq + 2];
        const float p3 = v[4 * kq + 3] * v[4 * kq + 3];
        a0 += p0 * w0.x + p1 * w0.y + p2 * w0.z + p3 * w0.w;
        a1 += p0 * w1.x + p1 * w1.y + p2 * w1.z + p3 * w1.w;
    }
#pragma unroll
    for (int o = 16; o > 0; o >>= 1) {
        a0 += __shfl_down_sync(0xffffffffu, a0, o);
        a1 += __shfl_down_sync(0xffffffffu, a1, o);
    }
    if (lane == 0) { red[wid] = a0; red[8 + wid] = a1; }
    __syncthreads();
    if (wid == 0 && lane < 16) {
        float rr = (lane < 8) ? red[lane] : red[8 + (lane & 7)];
#pragma unroll
        for (int o = 4; o > 0; o >>= 1)
            rr += __shfl_down_sync(0x0000ffffu, rr, o);
        if (lane == 0) out[0] = rr + b[0];
        if (lane == 8) out[1] = rr + b[1];
    }
}

extern "C" void kernel_launch(void* const* d_in, const int* in_sizes, int n_in,
                              void* d_out, int out_size) {
    const float* x = nullptr;
    const float* th = nullptr;
    const float* w = nullptr;
    const float* b = nullptr;
    for (int i = 0; i < n_in; ++i) {
        const int s = in_sizes[i];
        if (s == NQ) x = (const float*)d_in[i];
        else if (s == DEPTH * NQ) th = (const float*)d_in[i];
        else if (s == 2 * DIM) w = (const float*)d_in[i];
        else if (s == 2) b = (const float*)d_in[i];
    }
    qsim_kernel<<<1, 256>>>(x, th, w, b, (float*)d_out);
}